// round 17
// baseline (speedup 1.0000x reference)
#include <cuda_runtime.h>

#define Bq   256
#define Tq   1024
#define NUMq 126
#define LBLq 128

__device__ __forceinline__ void fma2(unsigned long long& d,
                                     unsigned long long a, unsigned long long b) {
    asm("fma.rn.f32x2 %0, %1, %2, %0;" : "+l"(d) : "l"(a), "l"(b));
}
__device__ __forceinline__ unsigned long long add2(unsigned long long a,
                                                   unsigned long long b) {
    unsigned long long d;
    asm("add.rn.f32x2 %0, %1, %2;" : "=l"(d) : "l"(a), "l"(b));
    return d;
}
__device__ __forceinline__ unsigned long long pack2(float lo, float hi) {
    unsigned long long d;
    asm("mov.b64 %0, {%1, %2};" : "=l"(d) : "f"(lo), "f"(hi));
    return d;
}
__device__ __forceinline__ void unpack2(unsigned long long d, float& lo, float& hi) {
    asm("mov.b64 {%0, %1}, %2;" : "=f"(lo), "=f"(hi) : "l"(d));
}
__device__ __forceinline__ int clampi(int t, int n) {
    int u = (t < n) ? t : (n - 1);
    return (u > 0) ? u : 0;
}

// One CTA = one sequence; fwd and bwd half-scans run as two interleaved
// streams under the same barrier. slot = blockIdx.x is the length rank.
__global__ __launch_bounds__(128, 2)
void crf_fused(const float* __restrict__ logits,
               const int*   __restrict__ labels,
               const int*   __restrict__ lens,
               const float* __restrict__ trans,
               float*       __restrict__ out) {
    const int slot = blockIdx.x;
    const int tid  = threadIdx.x;
    const int w    = tid >> 5;
    const int l    = tid & 31;
    const int h    = l >> 4;               // k-half (64 cols each)
    const int g    = l & 15;               // row-group within warp
    const int rowbase = w * 32 + g * 2;

    __shared__ __align__(128) float abufF[2][LBLq];
    __shared__ __align__(128) float abufB[2][LBLq];
    __shared__ float vA[LBLq], vB[LBLq];
    __shared__ int sl[Bq];
    __shared__ int s_b;
    __shared__ float red[4];

    // ---- in-CTA ranking: find b whose length-rank == slot ----
    sl[tid]       = lens[tid];
    sl[tid + 128] = lens[tid + 128];
    __syncthreads();
    #pragma unroll
    for (int half = 0; half < 2; ++half) {
        int cand = tid + half * 128;
        int lc = sl[cand];
        int r = 0;
        #pragma unroll 8
        for (int k = 0; k < Bq; ++k) {
            int lk = sl[k];
            r += (lk > lc) || (lk == lc && k < cand);
        }
        if (r == slot) s_b = cand;
    }
    __syncthreads();
    const int b   = s_b;
    const int len = sl[b];
    const int m   = (len - 1) >> 1;
    const int nF  = m;                 // fwd steps
    const int nB  = len - 1 - m;       // bwd steps (nB >= nF)
    const int mx  = nB;                // loop bound

    // ---- tiles: 2 rows x 64 cols of M (fwd) and of M^T (bwd) ----
    unsigned long long RF[2][32], RB[2][32];
    #pragma unroll
    for (int r = 0; r < 2; ++r) {
        const float4* trow = (const float4*)(trans + (rowbase + r) * LBLq + h * 64);
        #pragma unroll
        for (int s = 0; s < 16; ++s) {
            float4 v = trow[s];
            RF[r][2 * s]     = pack2(__expf(v.x), __expf(v.y));
            RF[r][2 * s + 1] = pack2(__expf(v.z), __expf(v.w));
        }
    }
    #pragma unroll
    for (int r = 0; r < 2; ++r) {
        const int k = rowbase + r;         // row of M^T = column of M
        #pragma unroll
        for (int s = 0; s < 16; ++s) {
            int j = h * 64 + 4 * s;
            RB[r][2 * s]     = pack2(__expf(trans[(j + 0) * LBLq + k]),
                                     __expf(trans[(j + 1) * LBLq + k]));
            RB[r][2 * s + 1] = pack2(__expf(trans[(j + 2) * LBLq + k]),
                                     __expf(trans[(j + 3) * LBLq + k]));
        }
    }
    float vmask[2];
    vmask[0] = (rowbase + 0 < NUMq) ? 1.f : 0.f;
    vmask[1] = (rowbase + 1 < NUMq) ? 1.f : 0.f;
    const int rr0 = (rowbase + 0 < NUMq) ? (rowbase + 0) : (NUMq - 1);
    const int rr1 = (rowbase + 1 < NUMq) ? (rowbase + 1) : (NUMq - 1);

    const int lb = b * Tq;
    const float* lgb = logits + (size_t)lb * NUMq;

    // ---- init ----
    abufF[0][tid] = (tid == (LBLq - 2)) ? 1.0f : 0.0f;
    abufB[0][tid] = (tid < NUMq)
        ? __expf(trans[(LBLq - 1) * LBLq + tid] + lgb[(len - 1) * NUMq + tid])
        : 0.f;

    // fwd logit index = t ; bwd logit index = len-2-t
    float curF[4][2], nxtF[4][2], weF[4][2];
    float curB[4][2], nxtB[4][2], weB[4][2];
    #pragma unroll
    for (int q = 0; q < 4; ++q) {
        int tf = clampi(q, nF), tb = clampi(q, nB);
        curF[q][0] = lgb[tf * NUMq + rr0];
        curF[q][1] = lgb[tf * NUMq + rr1];
        curB[q][0] = lgb[(len - 2 - tb) * NUMq + rr0];
        curB[q][1] = lgb[(len - 2 - tb) * NUMq + rr1];
        int tf2 = clampi(4 + q, nF), tb2 = clampi(4 + q, nB);
        nxtF[q][0] = lgb[tf2 * NUMq + rr0];
        nxtF[q][1] = lgb[tf2 * NUMq + rr1];
        nxtB[q][0] = lgb[(len - 2 - tb2) * NUMq + rr0];
        nxtB[q][1] = lgb[(len - 2 - tb2) * NUMq + rr1];
    }
    #pragma unroll
    for (int q = 0; q < 4; ++q) {
        weF[q][0] = __expf(curF[q][0]) * vmask[0];
        weF[q][1] = __expf(curF[q][1]) * vmask[1];
        weB[q][0] = __expf(curB[q][0]) * vmask[0];
        weB[q][1] = __expf(curB[q][1]) * vmask[1];
    }

    float logcF = 0.f, invF = 1.f;
    float logcB = 0.f, invB = 1.f;
    __syncthreads();

// One interval = one fwd step + one bwd step, single barrier.
#define STEP2(PH, T)                                                            \
    {                                                                           \
        const int rb = (PH) & 1, wb = 1 - rb;                                   \
        if ((PH) == 0 && (T) != 0) {                                            \
            _Pragma("unroll")                                                   \
            for (int q = 0; q < 4; ++q) {                                       \
                curF[q][0] = nxtF[q][0]; curF[q][1] = nxtF[q][1];               \
                curB[q][0] = nxtB[q][0]; curB[q][1] = nxtB[q][1];               \
                int tf = clampi((T) + 4 + q, nF);                               \
                int tb = clampi((T) + 4 + q, nB);                               \
                nxtF[q][0] = lgb[tf * NUMq + rr0];                              \
                nxtF[q][1] = lgb[tf * NUMq + rr1];                              \
                nxtB[q][0] = lgb[(len - 2 - tb) * NUMq + rr0];                  \
                nxtB[q][1] = lgb[(len - 2 - tb) * NUMq + rr1];                  \
            }                                                                   \
            _Pragma("unroll")                                                   \
            for (int q = 0; q < 4; ++q) {                                       \
                weF[q][0] = __expf(curF[q][0]) * vmask[0];                      \
                weF[q][1] = __expf(curF[q][1]) * vmask[1];                      \
                weB[q][0] = __expf(curB[q][0]) * vmask[0];                      \
                weB[q][1] = __expf(curB[q][1]) * vmask[1];                      \
            }                                                                   \
        }                                                                       \
        const ulonglong2* aF = (const ulonglong2*)(abufF[rb] + h * 64);         \
        const ulonglong2* aB = (const ulonglong2*)(abufB[rb] + h * 64);         \
        unsigned long long f00 = 0ull, f01 = 0ull, f10 = 0ull, f11 = 0ull;      \
        unsigned long long b00 = 0ull, b01 = 0ull, b10 = 0ull, b11 = 0ull;      \
        unsigned long long sF0 = 0ull, sF1 = 0ull, sB0 = 0ull, sB1 = 0ull;      \
        _Pragma("unroll")                                                       \
        for (int s = 0; s < 16; ++s) {                                          \
            ulonglong2 AF = aF[s];                                              \
            ulonglong2 AB = aB[s];                                              \
            if ((PH) == 0) {                                                    \
                sF0 = add2(sF0, AF.x); sF1 = add2(sF1, AF.y);                   \
                sB0 = add2(sB0, AB.x); sB1 = add2(sB1, AB.y);                   \
            }                                                                   \
            fma2(f00, RF[0][2 * s], AF.x); fma2(f01, RF[0][2 * s + 1], AF.y);   \
            fma2(f10, RF[1][2 * s], AF.x); fma2(f11, RF[1][2 * s + 1], AF.y);   \
            fma2(b00, RB[0][2 * s], AB.x); fma2(b01, RB[0][2 * s + 1], AB.y);   \
            fma2(b10, RB[1][2 * s], AB.x); fma2(b11, RB[1][2 * s + 1], AB.y);   \
        }                                                                       \
        if ((PH) == 0) {                                                        \
            float lo1, hi1, lo2, hi2;                                           \
            unpack2(add2(sF0, sF1), lo1, hi1);                                  \
            unpack2(add2(sB0, sB1), lo2, hi2);                                  \
            float tsF = lo1 + hi1, tsB = lo2 + hi2;                             \
            tsF += __shfl_xor_sync(0xffffffffu, tsF, 16);                       \
            tsB += __shfl_xor_sync(0xffffffffu, tsB, 16);                       \
            if ((T) < nF) { invF = __fdividef(1.f, tsF); logcF += __logf(tsF); }\
            if ((T) < nB) { invB = __fdividef(1.f, tsB); logcB += __logf(tsB); }\
        }                                                                       \
        float lo, hi, pf0, pf1, pb0, pb1;                                       \
        unpack2(add2(f00, f01), lo, hi); pf0 = lo + hi;                         \
        unpack2(add2(f10, f11), lo, hi); pf1 = lo + hi;                         \
        unpack2(add2(b00, b01), lo, hi); pb0 = lo + hi;                         \
        unpack2(add2(b10, b11), lo, hi); pb1 = lo + hi;                         \
        pf0 += __shfl_xor_sync(0xffffffffu, pf0, 16);                           \
        pf1 += __shfl_xor_sync(0xffffffffu, pf1, 16);                           \
        pb0 += __shfl_xor_sync(0xffffffffu, pb0, 16);                           \
        pb1 += __shfl_xor_sync(0xffffffffu, pb1, 16);                           \
        float wf0 = weF[(PH)][0], wf1 = weF[(PH)][1];                           \
        float wb0 = weB[(PH)][0], wb1 = weB[(PH)][1];                           \
        if ((PH) == 1) { wf0 *= invF; wf1 *= invF; wb0 *= invB; wb1 *= invB; }  \
        if (h == 0 && (T) < nF)                                                 \
            *(float2*)&abufF[wb][rowbase] = make_float2(wf0 * pf0, wf1 * pf1);  \
        if (h == 0 && (T) < nB)                                                 \
            *(float2*)&abufB[wb][rowbase] = make_float2(wb0 * pb0, wb1 * pb1);  \
        __syncthreads();                                                        \
    }

    int t0 = 0;
    for (; t0 + 4 <= mx; t0 += 4) {
        STEP2(0, t0)
        STEP2(1, t0 + 1)
        STEP2(2, t0 + 2)
        STEP2(3, t0 + 3)
    }
    const int rem = mx - t0;
    if (rem > 0) STEP2(0, t0)
    if (rem > 1) STEP2(1, t0 + 1)
    if (rem > 2) STEP2(2, t0 + 2)
#undef STEP2

    // pending inv if a stream ended right after a group head
    const float pendF = ((nF & 3) == 1) ? invF : 1.0f;
    const float pendB = ((nB & 3) == 1) ? invB : 1.0f;

    // vecA = alpha_m
    vA[tid] = abufF[nF & 1][tid] * pendF;

    // vecB = M^T u_{nB} (one extra unweighted matvec)
    {
        const ulonglong2* aB = (const ulonglong2*)(abufB[nB & 1] + h * 64);
        unsigned long long b00 = 0ull, b01 = 0ull, b10 = 0ull, b11 = 0ull;
        #pragma unroll
        for (int s = 0; s < 16; ++s) {
            ulonglong2 A = aB[s];
            fma2(b00, RB[0][2 * s], A.x); fma2(b01, RB[0][2 * s + 1], A.y);
            fma2(b10, RB[1][2 * s], A.x); fma2(b11, RB[1][2 * s + 1], A.y);
        }
        float lo, hi, ps0, ps1;
        unpack2(add2(b00, b01), lo, hi); ps0 = lo + hi;
        ps0 += __shfl_xor_sync(0xffffffffu, ps0, 16);
        unpack2(add2(b10, b11), lo, hi); ps1 = lo + hi;
        ps1 += __shfl_xor_sync(0xffffffffu, ps1, 16);
        if (h == 0) {
            vB[rowbase + 0] = ps0 * pendB;
            vB[rowbase + 1] = ps1 * pendB;
        }
    }

    // ---- gold score (full sequence, cooperative) ----
    float gacc = 0.f;
    for (int t = tid; t < len; t += 128) {
        int lab = labels[lb + t];
        gacc += lgb[t * NUMq + lab];
        int prev = (t == 0) ? (LBLq - 2) : labels[lb + t - 1];
        gacc += trans[lab * LBLq + prev];
    }
    if (tid == 0) gacc += trans[(LBLq - 1) * LBLq + labels[lb + len - 1]];
    __syncthreads();   // vA/vB ready

    // ---- dot + reductions ----
    float p = vA[tid] * vB[tid];
    #pragma unroll
    for (int d = 16; d >= 1; d >>= 1) {
        gacc += __shfl_xor_sync(0xffffffffu, gacc, d);
        p    += __shfl_xor_sync(0xffffffffu, p, d);
    }
    if (l == 0) { red[w] = gacc; vA[w] = p; }   // vA reused as scratch
    __syncthreads();
    if (tid == 0) {
        float gold = (red[0] + red[1]) + (red[2] + red[3]);
        float dot  = (vA[0] + vA[1]) + (vA[2] + vA[3]);
        out[b] = gold - (logcF + logcB + __logf(dot));
    }
}

extern "C" void kernel_launch(void* const* d_in, const int* in_sizes, int n_in,
                              void* d_out, int out_size) {
    const float* logits = (const float*)d_in[0];
    const int*   labels = (const int*)d_in[1];
    const int*   lens   = (const int*)d_in[2];
    const float* trans  = (const float*)d_in[3];
    float*       out    = (float*)d_out;

    crf_fused<<<Bq, 128>>>(logits, labels, lens, trans, out);
}